// round 2
// baseline (speedup 1.0000x reference)
#include <cuda_runtime.h>

// LSTM_74122545594502: 3-layer bidirectional LSTM, B=4096 T=256 D=4 H=16.
// Round 2 design: warp-synchronous. One warp = one (chain, direction).
// Lane l owns gate rows (l, l+32) packed into f32x2 (rows 0-15=i,16-31=f,
// 32-47=g,48-63=o -> lane l<16 holds (i_l,g_l), lane l+16 holds (f_l,o_l)).
// Weights register-resident as packed pairs. Inputs duplicated (v,v) in smem
// so LDS.128 feeds fma.rn.f32x2 directly. No __syncthreads anywhere.

namespace {
constexpr int B_ = 4096;
constexpr int T_ = 256;
constexpr int D_ = 4;
constexpr int H_ = 16;
constexpr int WARPS_CTA = 4;
constexpr int NCTA = (2 * B_) / WARPS_CTA;  // 2048
}

typedef unsigned long long ull;

__device__ __forceinline__ ull pack2(float x, float y) {
    ull r;
    asm("mov.b64 %0, {%1, %2};" : "=l"(r) : "f"(x), "f"(y));
    return r;
}
__device__ __forceinline__ void unpack2(ull v, float& x, float& y) {
    asm("mov.b64 {%0, %1}, %2;" : "=f"(x), "=f"(y) : "l"(v));
}
__device__ __forceinline__ ull ffma2(ull a, ull b, ull c) {
    ull d;
    asm("fma.rn.f32x2 %0, %1, %2, %3;" : "=l"(d) : "l"(a), "l"(b), "l"(c));
    return d;
}
__device__ __forceinline__ ull add2(ull a, ull b) {
    ull d;
    asm("add.rn.f32x2 %0, %1, %2;" : "=l"(d) : "l"(a), "l"(b));
    return d;
}

// sigmoid(v) = 1/(1+exp(-v)); tanh(v) = 2*sigmoid(2v)-1.
__device__ __forceinline__ float fast_act(float v, bool is_tanh) {
    float arg = is_tanh ? (-2.0f * v) : (-v);
    float e = __expf(arg);
    float r = __fdividef(1.0f, 1.0f + e);
    return is_tanh ? (2.0f * r - 1.0f) : r;
}

struct Params {
    const float* y;
    const float* w[24];  // dir*12 + {Wih1,Whh1,bih1,bhh1, Wih2,..., bhh3}
};

__device__ float g_h3[2][B_][H_];  // final layer-3 h, [dir][batch][unit]

struct __align__(16) WarpBuf {
    ull x[4];        // x duplicated (v,v), 4 values
    ull h[3][16];    // per-layer h duplicated
};

// Gate pre-activation for this lane's packed row pair.
// in_dup: IN duplicated inputs; h_dup: 16 duplicated h values.
template <int IN>
__device__ __forceinline__ ull gates(const ull* in_dup, const ull* h_dup,
                                     const ull* wih, const ull* whh, ull bias) {
    ull a0 = bias, a1 = 0ull, a2 = 0ull, a3 = 0ull;
#pragma unroll
    for (int j = 0; j < IN / 2; ++j) {
        ulonglong2 u = ((const ulonglong2*)in_dup)[j];
        a0 = ffma2(wih[2 * j], u.x, a0);
        a1 = ffma2(wih[2 * j + 1], u.y, a1);
    }
#pragma unroll
    for (int j = 0; j < 8; ++j) {
        ulonglong2 v = ((const ulonglong2*)h_dup)[j];
        a2 = ffma2(whh[2 * j], v.x, a2);
        a3 = ffma2(whh[2 * j + 1], v.y, a3);
    }
    return add2(add2(a0, a2), add2(a1, a3));
}

__global__ void __launch_bounds__(128) lstm_kernel(Params p) {
    __shared__ WarpBuf wb[WARPS_CTA];

    const int lane = threadIdx.x & 31;
    const int w    = threadIdx.x >> 5;
    const int gw   = blockIdx.x * WARPS_CTA + w;
    const int dir  = gw >> 12;           // 0: fwd, 1: bwd
    const int b    = gw & (B_ - 1);

    const float* const* ws = &p.w[dir * 12];
    const int rlo = lane, rhi = lane + 32;
    const bool tanh_hi = lane < 16;      // hi row is 'g' for lanes 0-15, 'o' else

    // Packed weights: (row_lo, row_hi) per input index.
    ull wih1[D_], whh1[H_], wih2[H_], whh2[H_], wih3[H_], whh3[H_];
#pragma unroll
    for (int j = 0; j < D_; ++j) wih1[j] = pack2(ws[0][rlo * D_ + j], ws[0][rhi * D_ + j]);
#pragma unroll
    for (int j = 0; j < H_; ++j) whh1[j] = pack2(ws[1][rlo * H_ + j], ws[1][rhi * H_ + j]);
    const ull b1p = pack2(ws[2][rlo] + ws[3][rlo], ws[2][rhi] + ws[3][rhi]);
#pragma unroll
    for (int j = 0; j < H_; ++j) wih2[j] = pack2(ws[4][rlo * H_ + j], ws[4][rhi * H_ + j]);
#pragma unroll
    for (int j = 0; j < H_; ++j) whh2[j] = pack2(ws[5][rlo * H_ + j], ws[5][rhi * H_ + j]);
    const ull b2p = pack2(ws[6][rlo] + ws[7][rlo], ws[6][rhi] + ws[7][rhi]);
#pragma unroll
    for (int j = 0; j < H_; ++j) wih3[j] = pack2(ws[8][rlo * H_ + j], ws[8][rhi * H_ + j]);
#pragma unroll
    for (int j = 0; j < H_; ++j) whh3[j] = pack2(ws[9][rlo * H_ + j], ws[9][rhi * H_ + j]);
    const ull b3p = pack2(ws[10][rlo] + ws[11][rlo], ws[10][rhi] + ws[11][rhi]);

    ull* xd  = wb[w].x;
    ull* hd0 = wb[w].h[0];
    ull* hd1 = wb[w].h[1];
    ull* hd2 = wb[w].h[2];

    // init state
    float c1 = 0.0f, c2 = 0.0f, c3 = 0.0f, h3v = 0.0f;
    if (lane < 16) { hd0[lane] = 0ull; hd1[lane] = 0ull; hd2[lane] = 0ull; }

    const float* yb = p.y + (size_t)b * T_ * D_;
    float4 xn = make_float4(0.f, 0.f, 0.f, 0.f);
    if (lane == 16) {
        int t0 = dir ? (T_ - 1) : 0;
        float4 x0 = *(const float4*)(yb + t0 * D_);
        xd[0] = pack2(x0.x, x0.x); xd[1] = pack2(x0.y, x0.y);
        xd[2] = pack2(x0.z, x0.z); xd[3] = pack2(x0.w, x0.w);
        int t1 = dir ? (T_ - 2) : 1;
        xn = *(const float4*)(yb + t1 * D_);
    }
    __syncwarp();

    const int srcl = (lane & 15) + 16;

    for (int step = 0; step < T_; ++step) {
        // ---------------- layer 1 ----------------
        {
            ull g = gates<D_>(xd, hd0, wih1, whh1, b1p);
            float glo, ghi;
            unpack2(g, glo, ghi);
            float alo = fast_act(glo, false);
            float ahi = fast_act(ghi, tanh_hi);
            float fv = __shfl_sync(0xffffffffu, alo, srcl);
            float ov = __shfl_sync(0xffffffffu, ahi, srcl);
            // lane 16: stage next x (all reads of xd completed before shfl)
            if (lane == 16 && step + 1 < T_) {
                xd[0] = pack2(xn.x, xn.x); xd[1] = pack2(xn.y, xn.y);
                xd[2] = pack2(xn.z, xn.z); xd[3] = pack2(xn.w, xn.w);
                if (step + 2 < T_) {
                    int tn = dir ? (T_ - 3 - step) : (step + 2);
                    xn = *(const float4*)(yb + tn * D_);
                }
            }
            if (lane < 16) {
                c1 = fmaf(fv, c1, alo * ahi);
                float h = ov * fast_act(c1, true);
                hd0[lane] = pack2(h, h);
            }
        }
        __syncwarp();

        // ---------------- layer 2 ----------------
        {
            ull g = gates<H_>(hd0, hd1, wih2, whh2, b2p);
            float glo, ghi;
            unpack2(g, glo, ghi);
            float alo = fast_act(glo, false);
            float ahi = fast_act(ghi, tanh_hi);
            float fv = __shfl_sync(0xffffffffu, alo, srcl);
            float ov = __shfl_sync(0xffffffffu, ahi, srcl);
            if (lane < 16) {
                c2 = fmaf(fv, c2, alo * ahi);
                float h = ov * fast_act(c2, true);
                hd1[lane] = pack2(h, h);
            }
        }
        __syncwarp();

        // ---------------- layer 3 ----------------
        {
            ull g = gates<H_>(hd1, hd2, wih3, whh3, b3p);
            float glo, ghi;
            unpack2(g, glo, ghi);
            float alo = fast_act(glo, false);
            float ahi = fast_act(ghi, tanh_hi);
            float fv = __shfl_sync(0xffffffffu, alo, srcl);
            float ov = __shfl_sync(0xffffffffu, ahi, srcl);
            if (lane < 16) {
                c3 = fmaf(fv, c3, alo * ahi);
                h3v = ov * fast_act(c3, true);
                hd2[lane] = pack2(h3v, h3v);
            }
        }
        __syncwarp();
    }

    if (lane < 16) g_h3[dir][b][lane] = h3v;
}

// out[b,k] = b_out[k] + sum_j W_out[k][j]*hf3[b][j] + W_out[k][16+j]*hb3[b][j]
__global__ void proj_kernel(const float* __restrict__ Wo,
                            const float* __restrict__ bo,
                            float* __restrict__ out) {
    int b = blockIdx.x * blockDim.x + threadIdx.x;
    if (b >= B_) return;
    float a0 = bo[0], a1 = bo[1], a2 = bo[2], a3 = bo[3];
#pragma unroll
    for (int j = 0; j < H_; ++j) {
        float hf = g_h3[0][b][j];
        a0 += Wo[0 * 32 + j] * hf;
        a1 += Wo[1 * 32 + j] * hf;
        a2 += Wo[2 * 32 + j] * hf;
        a3 += Wo[3 * 32 + j] * hf;
    }
#pragma unroll
    for (int j = 0; j < H_; ++j) {
        float hb = g_h3[1][b][j];
        a0 += Wo[0 * 32 + 16 + j] * hb;
        a1 += Wo[1 * 32 + 16 + j] * hb;
        a2 += Wo[2 * 32 + 16 + j] * hb;
        a3 += Wo[3 * 32 + 16 + j] * hb;
    }
    ((float4*)out)[b] = make_float4(a0, a1, a2, a3);
}

extern "C" void kernel_launch(void* const* d_in, const int* in_sizes, int n_in,
                              void* d_out, int out_size) {
    (void)in_sizes; (void)n_in; (void)out_size;
    Params p;
    p.y = (const float*)d_in[0];
    for (int i = 0; i < 24; ++i) p.w[i] = (const float*)d_in[1 + i];

    lstm_kernel<<<NCTA, 128>>>(p);
    proj_kernel<<<(B_ + 127) / 128, 128>>>((const float*)d_in[25],
                                           (const float*)d_in[26],
                                           (float*)d_out);
}

// round 3
// speedup vs baseline: 1.4913x; 1.4913x over previous
#include <cuda_runtime.h>

// LSTM_74122545594502: 3-layer bidirectional LSTM, B=4096 T=256 D=4 H=16.
// Round 3: round-1 dataflow (group of 64 threads owns 8 chains; thread t owns
// gate row t, scalar weights in registers, chains packed in f32x2), fixed:
//  - 128-thread CTA = 2 independent groups -> all 4 SMSPs used
//  - named barriers (bar.sync id,64) per group
//  - c/h update parallelized across all 64 threads (2 chains each)

namespace {
constexpr int B_ = 4096;
constexpr int T_ = 256;
constexpr int D_ = 4;
constexpr int H_ = 16;
constexpr int NB = 8;                       // chains per group
constexpr int GROUPS_PER_DIR = B_ / NB;     // 512
constexpr int NCTA = 2 * GROUPS_PER_DIR / 2;  // 512 CTAs, 2 groups each
}

typedef unsigned long long ull;

__device__ __forceinline__ ull pack2(float x, float y) {
    ull r;
    asm("mov.b64 %0, {%1, %2};" : "=l"(r) : "f"(x), "f"(y));
    return r;
}
__device__ __forceinline__ void unpack2(ull v, float& x, float& y) {
    asm("mov.b64 {%0, %1}, %2;" : "=f"(x), "=f"(y) : "l"(v));
}
__device__ __forceinline__ ull ffma2(ull a, ull b, ull c) {
    ull d;
    asm("fma.rn.f32x2 %0, %1, %2, %3;" : "=l"(d) : "l"(a), "l"(b), "l"(c));
    return d;
}

// sigmoid(v) = 1/(1+exp(-v)); tanh(v) = 2*sigmoid(2v)-1.
__device__ __forceinline__ float fast_act(float v, bool is_tanh) {
    float arg = is_tanh ? (-2.0f * v) : (-v);
    float e = __expf(arg);
    float r = __fdividef(1.0f, 1.0f + e);
    return is_tanh ? (2.0f * r - 1.0f) : r;
}
__device__ __forceinline__ float fast_tanh(float v) { return fast_act(v, true); }

struct Params {
    const float* y;
    const float* w[24];  // dir*12 + {Wih1,Whh1,bih1,bhh1, Wih2,...,bhh3}
};

__device__ float g_h3[2][B_][H_];  // final layer-3 h

// 64 gate pre-activations (this thread's row t) over NB chains, activate,
// store to gates row. in_sm: [IN][NB] (rows 32B, 16B-aligned).
template <int IN>
__device__ __forceinline__ void gates_stage(
    const float* in_sm, const float* h_in,
    const float* wih, const float* whh, ull bias_pack,
    float* gates_row, bool is_tanh)
{
    ull a0 = bias_pack, a1 = bias_pack, a2 = bias_pack, a3 = bias_pack;
#pragma unroll
    for (int j = 0; j < IN; ++j) {
        ull wp = pack2(wih[j], wih[j]);
        ulonglong2 v01 = *(const ulonglong2*)(in_sm + j * NB);
        ulonglong2 v23 = *(const ulonglong2*)(in_sm + j * NB + 4);
        a0 = ffma2(wp, v01.x, a0);
        a1 = ffma2(wp, v01.y, a1);
        a2 = ffma2(wp, v23.x, a2);
        a3 = ffma2(wp, v23.y, a3);
    }
#pragma unroll
    for (int j = 0; j < H_; ++j) {
        ull wp = pack2(whh[j], whh[j]);
        ulonglong2 v01 = *(const ulonglong2*)(h_in + j * NB);
        ulonglong2 v23 = *(const ulonglong2*)(h_in + j * NB + 4);
        a0 = ffma2(wp, v01.x, a0);
        a1 = ffma2(wp, v01.y, a1);
        a2 = ffma2(wp, v23.x, a2);
        a3 = ffma2(wp, v23.y, a3);
    }
    float g0, g1, g2, g3, g4, g5, g6, g7;
    unpack2(a0, g0, g1);
    unpack2(a1, g2, g3);
    unpack2(a2, g4, g5);
    unpack2(a3, g6, g7);
    float4 r0 = make_float4(fast_act(g0, is_tanh), fast_act(g1, is_tanh),
                            fast_act(g2, is_tanh), fast_act(g3, is_tanh));
    float4 r1 = make_float4(fast_act(g4, is_tanh), fast_act(g5, is_tanh),
                            fast_act(g6, is_tanh), fast_act(g7, is_tanh));
    *(float4*)(gates_row + 0) = r0;
    *(float4*)(gates_row + 4) = r1;
}

// c/h update for (unit l, chains 2cp, 2cp+1). gsm rows are 12-float pitch.
__device__ __forceinline__ void update_stage(
    const float (*gsm)[12], int l, int cp,
    float& ca, float& cb, float* h_dst)
{
    float2 iv = *(const float2*)(&gsm[l][2 * cp]);
    float2 fv = *(const float2*)(&gsm[l + 16][2 * cp]);
    float2 gv = *(const float2*)(&gsm[l + 32][2 * cp]);
    float2 ov = *(const float2*)(&gsm[l + 48][2 * cp]);
    ca = fmaf(fv.x, ca, iv.x * gv.x);
    cb = fmaf(fv.y, cb, iv.y * gv.y);
    float2 h = make_float2(ov.x * fast_tanh(ca), ov.y * fast_tanh(cb));
    *(float2*)h_dst = h;
}

__global__ __launch_bounds__(128) void lstm_kernel(Params p) {
    __shared__ float x_sm[2][2][D_][NB];       // [group][buf][j][c]
    __shared__ float h_sm[2][3][H_][NB];       // [group][layer][j][c]
    __shared__ float gates_sm[2][64][12];      // 12-float pitch

    const int tid  = threadIdx.x;
    const int g    = tid >> 6;                 // group within CTA
    const int t    = tid & 63;                 // thread within group
    const int ggid = blockIdx.x * 2 + g;       // global group id
    const int dir  = ggid >> 9;
    const int b0   = (ggid & 511) * NB;
    const bool tanh_row = ((t >> 4) == 2);     // rows 32..47 are 'g'

    const float* const* ws = &p.w[dir * 12];

    // Per-thread weights for gate row t, all 3 layers.
    float wih1[D_], whh1[H_], wih2[H_], whh2[H_], wih3[H_], whh3[H_];
#pragma unroll
    for (int j = 0; j < D_; ++j) wih1[j] = ws[0][t * D_ + j];
#pragma unroll
    for (int j = 0; j < H_; ++j) whh1[j] = ws[1][t * H_ + j];
    const float b1 = ws[2][t] + ws[3][t];
#pragma unroll
    for (int j = 0; j < H_; ++j) wih2[j] = ws[4][t * H_ + j];
#pragma unroll
    for (int j = 0; j < H_; ++j) whh2[j] = ws[5][t * H_ + j];
    const float b2 = ws[6][t] + ws[7][t];
#pragma unroll
    for (int j = 0; j < H_; ++j) wih3[j] = ws[8][t * H_ + j];
#pragma unroll
    for (int j = 0; j < H_; ++j) whh3[j] = ws[9][t * H_ + j];
    const float b3 = ws[10][t] + ws[11][t];

    const ull b1p = pack2(b1, b1);
    const ull b2p = pack2(b2, b2);
    const ull b3p = pack2(b3, b3);

    // Update-stage ownership: unit l, chain pair cp.
    const int l  = t & 15;
    const int cp = t >> 4;
    float c1a = 0.f, c1b = 0.f, c2a = 0.f, c2b = 0.f, c3a = 0.f, c3b = 0.f;

    // zero h state for this group
    for (int i = t; i < 3 * H_ * NB; i += 64) (&h_sm[g][0][0][0])[i] = 0.0f;

    // stage x for step 0 (threads 0..31: one (c,j) each)
    const int pc = t >> 2, pj = t & 3;  // prefetch coords for t<32
    if (t < 32) {
        int tt = dir ? (T_ - 1) : 0;
        x_sm[g][0][pj][pc] = p.y[((size_t)(b0 + pc) * T_ + tt) * D_ + pj];
    }
    asm volatile("bar.sync %0, 64;" :: "r"(g + 1) : "memory");

    const float (*gsm)[12] = gates_sm[g];

    for (int step = 0; step < T_; ++step) {
        const int buf = step & 1;

        // issue next-x LDG early (latency hidden behind layer-1 gates)
        float xnext = 0.0f;
        if (t < 32 && step + 1 < T_) {
            int tt = dir ? (T_ - 2 - step) : (step + 1);
            xnext = p.y[((size_t)(b0 + pc) * T_ + tt) * D_ + pj];
        }

        // ---------- layer 1 ----------
        gates_stage<D_>(&x_sm[g][buf][0][0], &h_sm[g][0][0][0],
                        wih1, whh1, b1p, (float*)&gates_sm[g][t][0], tanh_row);
        asm volatile("bar.sync %0, 64;" :: "r"(g + 1) : "memory");
        update_stage(gsm, l, cp, c1a, c1b, &h_sm[g][0][l][2 * cp]);
        if (t < 32 && step + 1 < T_) x_sm[g][buf ^ 1][pj][pc] = xnext;
        asm volatile("bar.sync %0, 64;" :: "r"(g + 1) : "memory");

        // ---------- layer 2 ----------
        gates_stage<H_>(&h_sm[g][0][0][0], &h_sm[g][1][0][0],
                        wih2, whh2, b2p, (float*)&gates_sm[g][t][0], tanh_row);
        asm volatile("bar.sync %0, 64;" :: "r"(g + 1) : "memory");
        update_stage(gsm, l, cp, c2a, c2b, &h_sm[g][1][l][2 * cp]);
        asm volatile("bar.sync %0, 64;" :: "r"(g + 1) : "memory");

        // ---------- layer 3 ----------
        gates_stage<H_>(&h_sm[g][1][0][0], &h_sm[g][2][0][0],
                        wih3, whh3, b3p, (float*)&gates_sm[g][t][0], tanh_row);
        asm volatile("bar.sync %0, 64;" :: "r"(g + 1) : "memory");
        update_stage(gsm, l, cp, c3a, c3b, &h_sm[g][2][l][2 * cp]);
        asm volatile("bar.sync %0, 64;" :: "r"(g + 1) : "memory");
    }

    // write final layer-3 h to scratch
    for (int i = t; i < H_ * NB; i += 64) {
        int j = i / NB, c = i % NB;
        g_h3[dir][b0 + c][j] = h_sm[g][2][j][c];
    }
}

// out[b,k] = b_out[k] + sum_j W_out[k][j]*hf3[b][j] + W_out[k][16+j]*hb3[b][j]
__global__ void proj_kernel(const float* __restrict__ Wo,
                            const float* __restrict__ bo,
                            float* __restrict__ out) {
    int b = blockIdx.x * blockDim.x + threadIdx.x;
    if (b >= B_) return;
    float a0 = bo[0], a1 = bo[1], a2 = bo[2], a3 = bo[3];
#pragma unroll
    for (int j = 0; j < H_; ++j) {
        float hf = g_h3[0][b][j];
        a0 += Wo[0 * 32 + j] * hf;
        a1 += Wo[1 * 32 + j] * hf;
        a2 += Wo[2 * 32 + j] * hf;
        a3 += Wo[3 * 32 + j] * hf;
    }
#pragma unroll
    for (int j = 0; j < H_; ++j) {
        float hb = g_h3[1][b][j];
        a0 += Wo[0 * 32 + 16 + j] * hb;
        a1 += Wo[1 * 32 + 16 + j] * hb;
        a2 += Wo[2 * 32 + 16 + j] * hb;
        a3 += Wo[3 * 32 + 16 + j] * hb;
    }
    ((float4*)out)[b] = make_float4(a0, a1, a2, a3);
}

extern "C" void kernel_launch(void* const* d_in, const int* in_sizes, int n_in,
                              void* d_out, int out_size) {
    (void)in_sizes; (void)n_in; (void)out_size;
    Params p;
    p.y = (const float*)d_in[0];
    for (int i = 0; i < 24; ++i) p.w[i] = (const float*)d_in[1 + i];

    lstm_kernel<<<NCTA, 128>>>(p);
    proj_kernel<<<(B_ + 127) / 128, 128>>>((const float*)d_in[25],
                                           (const float*)d_in[26],
                                           (float*)d_out);
}

// round 4
// speedup vs baseline: 1.9569x; 1.3122x over previous
#include <cuda_runtime.h>

// LSTM_74122545594502: 3-layer bidirectional LSTM, B=4096 T=256 D=4 H=16.
// Round 4: barrier-free warp-synchronous. One warp = 4 chains of one
// direction. Lane l owns gate rows (l, l+32): lane<16 -> (i_l, g_l),
// lane l+16 -> (f_l, o_l)  => all 4 gates of unit l in one lane pair;
// update via one shfl.bfly(16). L1 weights in regs; L2/L3 weights in a
// per-CTA smem table shared by the 4 warps (same direction per CTA).
// h double-buffered in smem; chains packed in f32x2 accumulators.

namespace {
constexpr int B_ = 4096;
constexpr int T_ = 256;
constexpr int D_ = 4;
constexpr int H_ = 16;
constexpr int NB = 4;                     // chains per warp
constexpr int WPC = 4;                    // warps per CTA
constexpr int GPD = B_ / NB;              // 1024 groups per direction
constexpr int NCTA = 2 * GPD / WPC;       // 512
constexpr int WPITCH = 36;                // weight row pitch in floats
}

typedef unsigned long long ull;

__device__ __forceinline__ ull pack2(float x, float y) {
    ull r;
    asm("mov.b64 %0, {%1, %2};" : "=l"(r) : "f"(x), "f"(y));
    return r;
}
__device__ __forceinline__ void unpack2(ull v, float& x, float& y) {
    asm("mov.b64 {%0, %1}, %2;" : "=f"(x), "=f"(y) : "l"(v));
}
__device__ __forceinline__ ull ffma2(ull a, ull b, ull c) {
    ull d;
    asm("fma.rn.f32x2 %0, %1, %2, %3;" : "=l"(d) : "l"(a), "l"(b), "l"(c));
    return d;
}
__device__ __forceinline__ ull mul2(ull a, ull b) {
    ull d;
    asm("mul.rn.f32x2 %0, %1, %2;" : "=l"(d) : "l"(a), "l"(b));
    return d;
}

// sigmoid(v) = 1/(1+exp(-v)); tanh(v) = 2*sigmoid(2v)-1.
__device__ __forceinline__ float fast_act(float v, bool is_tanh) {
    float arg = is_tanh ? (-2.0f * v) : (-v);
    float e = __expf(arg);
    float r = __fdividef(1.0f, 1.0f + e);
    return is_tanh ? (2.0f * r - 1.0f) : r;
}
__device__ __forceinline__ float fast_tanh(float v) { return fast_act(v, true); }

struct Params {
    const float* y;
    const float* w[24];  // dir*12 + {Wih1,Whh1,bih1,bhh1, Wih2,...,bhh3}
};

__device__ float g_h3[2][B_][H_];  // final layer-3 h

// One FFMA2 step: weight pairs (w,w) per row, input (c0,c1),(c2,c3).
__device__ __forceinline__ void gstep(ull wp0, ull wp1, ulonglong2 v,
                                      ull& a00, ull& a01, ull& a10, ull& a11) {
    a00 = ffma2(wp0, v.x, a00);
    a01 = ffma2(wp0, v.y, a01);
    a10 = ffma2(wp1, v.x, a10);
    a11 = ffma2(wp1, v.y, a11);
}

// Activate + cross-lane exchange + c/h update. Returns packed h pair
// (chains 0,1 for low lanes; 2,3 for high) and stores it to hdst (8B).
__device__ __forceinline__ ull do_update(ull a00, ull a01, ull a10, ull a11,
                                         bool low, ull& cst, float* hdst) {
    float p0, p1, p2, p3, q0, q1, q2, q3;
    unpack2(a00, p0, p1); unpack2(a01, p2, p3);
    unpack2(a10, q0, q1); unpack2(a11, q2, q3);
    // r0 rows (i or f): sigmoid. r1 rows: g (tanh) for low, o (sigmoid) for high.
    p0 = fast_act(p0, false); p1 = fast_act(p1, false);
    p2 = fast_act(p2, false); p3 = fast_act(p3, false);
    q0 = fast_act(q0, low);   q1 = fast_act(q1, low);
    q2 = fast_act(q2, low);   q3 = fast_act(q3, low);
    ull A01 = pack2(p0, p1), A23 = pack2(p2, p3);
    ull B01 = pack2(q0, q1), B23 = pack2(q2, q3);
    ull sA = low ? A23 : A01;
    ull sB = low ? B23 : B01;
    ull rA = __shfl_xor_sync(0xffffffffu, sA, 16);
    ull rB = __shfl_xor_sync(0xffffffffu, sB, 16);
    ull I = low ? A01 : rA;
    ull F = low ? rA : A23;
    ull G = low ? B01 : rB;
    ull O = low ? rB : B23;
    cst = ffma2(F, cst, mul2(I, G));
    float ca, cb, o0, o1;
    unpack2(cst, ca, cb);
    unpack2(O, o0, o1);
    ull hv = pack2(o0 * fast_tanh(ca), o1 * fast_tanh(cb));
    *(ull*)hdst = hv;
    return hv;
}

__global__ void __launch_bounds__(128, 4) lstm_kernel(Params p) {
    __shared__ float  wsm[2][64][WPITCH];   // L2/L3 weights [layer][row][0-15 ih |16-31 hh]
    __shared__ float4 xs[WPC][2][D_];       // [warp][buf][j] = 4 chains
    __shared__ float4 hs[WPC][3][2][H_];    // [warp][layer][buf][j] = 4 chains

    const int tid  = threadIdx.x;
    const int lane = tid & 31;
    const int w    = tid >> 5;
    const int dir  = blockIdx.x >> 8;
    const int gidx = (blockIdx.x & 255) * WPC + w;
    const int b0   = gidx * NB;
    const bool low = lane < 16;
    const int unit = lane & 15;

    const float* const* ws = &p.w[dir * 12];

    // ---- cooperative fill of L2/L3 weight table ----
    for (int i = tid; i < 2 * 64 * 32; i += 128) {
        int layer = i >> 11, rem = i & 2047, row = rem >> 5, col = rem & 31;
        float v = (col < 16) ? ws[4 + layer * 4][row * 16 + col]
                             : ws[5 + layer * 4][row * 16 + (col - 16)];
        wsm[layer][row][col] = v;
    }

    // ---- L1 weights + all biases in registers ----
    const int r0 = lane, r1 = lane + 32;
    float wi0[D_], wi1[D_], wh0[H_], wh1[H_];
#pragma unroll
    for (int j = 0; j < D_; ++j) { wi0[j] = ws[0][r0 * D_ + j]; wi1[j] = ws[0][r1 * D_ + j]; }
#pragma unroll
    for (int j = 0; j < H_; ++j) { wh0[j] = ws[1][r0 * H_ + j]; wh1[j] = ws[1][r1 * H_ + j]; }
    float b10 = ws[2][r0] + ws[3][r0], b11 = ws[2][r1] + ws[3][r1];
    float b20 = ws[6][r0] + ws[7][r0], b21 = ws[6][r1] + ws[7][r1];
    float b30 = ws[10][r0] + ws[11][r0], b31 = ws[10][r1] + ws[11][r1];
    const ull bp10 = pack2(b10, b10), bp11 = pack2(b11, b11);
    const ull bp20 = pack2(b20, b20), bp21 = pack2(b21, b21);
    const ull bp30 = pack2(b30, b30), bp31 = pack2(b31, b31);

    // ---- init h (buf 0) and x (buf 0) ----
    if (low) {
        float4 z = make_float4(0.f, 0.f, 0.f, 0.f);
        hs[w][0][0][unit] = z; hs[w][1][0][unit] = z; hs[w][2][0][unit] = z;
        int c = lane >> 2, j = lane & 3;
        int tt = dir ? (T_ - 1) : 0;
        ((float*)&xs[w][0][j])[c] = p.y[((size_t)(b0 + c) * T_ + tt) * D_ + j];
    }
    __syncthreads();  // weights table + init visible

    ull c1 = 0ull, c2 = 0ull, c3 = 0ull, h3out = 0ull;
    const int xc = lane >> 2, xj = lane & 3;  // x prefetch coords (low lanes)

    for (int step = 0; step < T_; ++step) {
        const int buf = step & 1, nbuf = buf ^ 1;

        // early next-x load (latency hidden under L1 gates)
        float xn = 0.0f;
        if (low && step + 1 < T_) {
            int tt = dir ? (T_ - 2 - step) : (step + 1);
            xn = p.y[((size_t)(b0 + xc) * T_ + tt) * D_ + xj];
        }

        // ---------------- layer 1 (weights in regs) ----------------
        {
            ull a00 = bp10, a01 = bp10, a10 = bp11, a11 = bp11;
            const ulonglong2* xv = (const ulonglong2*)&xs[w][buf][0];
#pragma unroll
            for (int j = 0; j < D_; ++j)
                gstep(pack2(wi0[j], wi0[j]), pack2(wi1[j], wi1[j]), xv[j],
                      a00, a01, a10, a11);
            const ulonglong2* hv = (const ulonglong2*)&hs[w][0][buf][0];
#pragma unroll
            for (int j = 0; j < H_; ++j)
                gstep(pack2(wh0[j], wh0[j]), pack2(wh1[j], wh1[j]), hv[j],
                      a00, a01, a10, a11);
            float* hd = (float*)&hs[w][0][nbuf][unit] + (low ? 0 : 2);
            do_update(a00, a01, a10, a11, low, c1, hd);
        }
        if (low && step + 1 < T_) ((float*)&xs[w][nbuf][xj])[xc] = xn;
        __syncwarp();

        // ---------------- layer 2 (weights from smem) ----------------
        {
            ull a00 = bp20, a01 = bp20, a10 = bp21, a11 = bp21;
            const ulonglong2* in0 = (const ulonglong2*)&hs[w][0][nbuf][0];
            const ulonglong2* in1 = (const ulonglong2*)&hs[w][1][buf][0];
#pragma unroll
            for (int jq = 0; jq < 4; ++jq) {
                float4 w0 = *(const float4*)&wsm[0][r0][4 * jq];
                float4 w1 = *(const float4*)&wsm[0][r1][4 * jq];
                gstep(pack2(w0.x, w0.x), pack2(w1.x, w1.x), in0[4 * jq + 0], a00, a01, a10, a11);
                gstep(pack2(w0.y, w0.y), pack2(w1.y, w1.y), in0[4 * jq + 1], a00, a01, a10, a11);
                gstep(pack2(w0.z, w0.z), pack2(w1.z, w1.z), in0[4 * jq + 2], a00, a01, a10, a11);
                gstep(pack2(w0.w, w0.w), pack2(w1.w, w1.w), in0[4 * jq + 3], a00, a01, a10, a11);
            }
#pragma unroll
            for (int jq = 0; jq < 4; ++jq) {
                float4 w0 = *(const float4*)&wsm[0][r0][16 + 4 * jq];
                float4 w1 = *(const float4*)&wsm[0][r1][16 + 4 * jq];
                gstep(pack2(w0.x, w0.x), pack2(w1.x, w1.x), in1[4 * jq + 0], a00, a01, a10, a11);
                gstep(pack2(w0.y, w0.y), pack2(w1.y, w1.y), in1[4 * jq + 1], a00, a01, a10, a11);
                gstep(pack2(w0.z, w0.z), pack2(w1.z, w1.z), in1[4 * jq + 2], a00, a01, a10, a11);
                gstep(pack2(w0.w, w0.w), pack2(w1.w, w1.w), in1[4 * jq + 3], a00, a01, a10, a11);
            }
            float* hd = (float*)&hs[w][1][nbuf][unit] + (low ? 0 : 2);
            do_update(a00, a01, a10, a11, low, c2, hd);
        }
        __syncwarp();

        // ---------------- layer 3 (weights from smem) ----------------
        {
            ull a00 = bp30, a01 = bp30, a10 = bp31, a11 = bp31;
            const ulonglong2* in0 = (const ulonglong2*)&hs[w][1][nbuf][0];
            const ulonglong2* in1 = (const ulonglong2*)&hs[w][2][buf][0];
#pragma unroll
            for (int jq = 0; jq < 4; ++jq) {
                float4 w0 = *(const float4*)&wsm[1][r0][4 * jq];
                float4 w1 = *(const float4*)&wsm[1][r1][4 * jq];
                gstep(pack2(w0.x, w0.x), pack2(w1.x, w1.x), in0[4 * jq + 0], a00, a01, a10, a11);
                gstep(pack2(w0.y, w0.y), pack2(w1.y, w1.y), in0[4 * jq + 1], a00, a01, a10, a11);
                gstep(pack2(w0.z, w0.z), pack2(w1.z, w1.z), in0[4 * jq + 2], a00, a01, a10, a11);
                gstep(pack2(w0.w, w0.w), pack2(w1.w, w1.w), in0[4 * jq + 3], a00, a01, a10, a11);
            }
#pragma unroll
            for (int jq = 0; jq < 4; ++jq) {
                float4 w0 = *(const float4*)&wsm[1][r0][16 + 4 * jq];
                float4 w1 = *(const float4*)&wsm[1][r1][16 + 4 * jq];
                gstep(pack2(w0.x, w0.x), pack2(w1.x, w1.x), in1[4 * jq + 0], a00, a01, a10, a11);
                gstep(pack2(w0.y, w0.y), pack2(w1.y, w1.y), in1[4 * jq + 1], a00, a01, a10, a11);
                gstep(pack2(w0.z, w0.z), pack2(w1.z, w1.z), in1[4 * jq + 2], a00, a01, a10, a11);
                gstep(pack2(w0.w, w0.w), pack2(w1.w, w1.w), in1[4 * jq + 3], a00, a01, a10, a11);
            }
            float* hd = (float*)&hs[w][2][nbuf][unit] + (low ? 0 : 2);
            h3out = do_update(a00, a01, a10, a11, low, c3, hd);
        }
        __syncwarp();
    }

    // final layer-3 h: low lane has chains 0,1 of its unit; high has 2,3.
    {
        float h0f, h1f;
        unpack2(h3out, h0f, h1f);
        int c = low ? 0 : 2;
        g_h3[dir][b0 + c][unit]     = h0f;
        g_h3[dir][b0 + c + 1][unit] = h1f;
    }
}

// out[b,k] = b_out[k] + sum_j W_out[k][j]*hf3[b][j] + W_out[k][16+j]*hb3[b][j]
__global__ void proj_kernel(const float* __restrict__ Wo,
                            const float* __restrict__ bo,
                            float* __restrict__ out) {
    int b = blockIdx.x * blockDim.x + threadIdx.x;
    if (b >= B_) return;
    float a0 = bo[0], a1 = bo[1], a2 = bo[2], a3 = bo[3];
#pragma unroll
    for (int j = 0; j < H_; ++j) {
        float hf = g_h3[0][b][j];
        a0 += Wo[0 * 32 + j] * hf;
        a1 += Wo[1 * 32 + j] * hf;
        a2 += Wo[2 * 32 + j] * hf;
        a3 += Wo[3 * 32 + j] * hf;
    }
#pragma unroll
    for (int j = 0; j < H_; ++j) {
        float hb = g_h3[1][b][j];
        a0 += Wo[0 * 32 + 16 + j] * hb;
        a1 += Wo[1 * 32 + 16 + j] * hb;
        a2 += Wo[2 * 32 + 16 + j] * hb;
        a3 += Wo[3 * 32 + 16 + j] * hb;
    }
    ((float4*)out)[b] = make_float4(a0, a1, a2, a3);
}

extern "C" void kernel_launch(void* const* d_in, const int* in_sizes, int n_in,
                              void* d_out, int out_size) {
    (void)in_sizes; (void)n_in; (void)out_size;
    Params p;
    p.y = (const float*)d_in[0];
    for (int i = 0; i < 24; ++i) p.w[i] = (const float*)d_in[1 + i];

    lstm_kernel<<<NCTA, 128>>>(p);
    proj_kernel<<<(B_ + 127) / 128, 128>>>((const float*)d_in[25],
                                           (const float*)d_in[26],
                                           (float*)d_out);
}